// round 13
// baseline (speedup 1.0000x reference)
#include <cuda_runtime.h>
#include <cuda_fp16.h>
#include <cstdint>

// ============================================================================
// probs[x,y,z] = sum_{i,j,k} A[j,k,x]Pb[j]Pc[k] * B[k,i,y]Pa[i] * C[i,j,z]
// K=512, O=8.
//  1) conv:  Ahf[j*8+x,k] = fp16(A[j,k,x]*Pb[j]*Pc[k])
//            Bhf[i*8+y,k] = fp16(B[k,i,y]*Pa[i])
//  2) gemm:  D[m,n] = sum_k Ahf[m,k]*Bhf[n,k]  (4096x4096x512, mma.sync fp16
//            acc). CTA tile 128x128, 4 warps (warp tile 64x64, 64-reg acc),
//            SPLIT-K=1 (grid 1024 -> epilogue FFMA halved vs split-K=2),
//            K=512 in 8 chunks of 64, 2-buffer ping-pong, 3 CTAs/SM
//            (12 warps/SM; barriers hidden by CTA overlap),
//            fused epilogue probs += D*C, fused last-block KL finalize.
// ============================================================================

__device__ __half g_Ahf[4096ull * 512];
__device__ __half g_Bhf[4096ull * 512];
__device__ float g_probs[512];
__device__ unsigned g_ctr;

__device__ __forceinline__ uint32_t smem_u32(const void* p) {
    uint32_t a;
    asm("{ .reg .u64 t; cvta.to.shared.u64 t, %1; cvt.u32.u64 %0, t; }" : "=r"(a) : "l"(p));
    return a;
}

#define SWZ128(off) ((off) ^ (((off) >> 3) & 0x70))

__device__ __forceinline__ void ldmatrix_x4(uint32_t addr, uint32_t& r0, uint32_t& r1,
                                            uint32_t& r2, uint32_t& r3) {
    asm volatile("ldmatrix.sync.aligned.m8n8.x4.shared.b16 {%0,%1,%2,%3}, [%4];"
                 : "=r"(r0), "=r"(r1), "=r"(r2), "=r"(r3) : "r"(addr));
}

// fp16-accumulate MMA: D(2xb32 = 4 halves) += A(4xb32) * B(2xb32)
__device__ __forceinline__ void mma16816_f16(uint32_t* d, const uint32_t* a,
                                             uint32_t b0, uint32_t b1) {
    asm volatile(
        "mma.sync.aligned.m16n8k16.row.col.f16.f16.f16.f16 "
        "{%0,%1}, {%2,%3,%4,%5}, {%6,%7}, {%0,%1};"
        : "+r"(d[0]), "+r"(d[1])
        : "r"(a[0]), "r"(a[1]), "r"(a[2]), "r"(a[3]), "r"(b0), "r"(b1));
}

__device__ __forceinline__ void cp_async16(uint32_t dst, const void* src) {
    asm volatile("cp.async.cg.shared.global [%0], [%1], 16;"
                 :: "r"(dst), "l"(src) : "memory");
}
#define CP_COMMIT() asm volatile("cp.async.commit_group;" ::: "memory")
#define CP_WAIT(n)  asm volatile("cp.async.wait_group %0;" :: "n"(n) : "memory")

// ============================================================================
// Kernel 1: fold scales + transpose + convert to fp16 K-major operands.
// ============================================================================
__global__ void __launch_bounds__(256) conv_kernel(const float* __restrict__ y_pred) {
    __shared__ float s[512 * 9];   // k-major, stride 9 (conflict-free transpose)
    const int tid = threadIdx.x;
    const int bid = blockIdx.x;

    if (bid == 0) {
        for (int i = tid; i < 512; i += 256) g_probs[i] = 0.0f;
        if (tid == 0) g_ctr = 0;
    }

    const float* Pa = y_pred;
    const float* Pb = y_pred + 512;
    const float* Pc = y_pred + 1024;
    const float* A  = y_pred + 1536;
    const float* B  = A + 512ull * 4096;

    if (bid < 512) {
        const int j = bid;
        const float4* src = (const float4*)(A + (size_t)j * 4096);
        #pragma unroll
        for (int u = 0; u < 4; ++u) {
            int v = tid + u * 256;           // 1024 float4 = 4096 floats (k,x)
            float4 d = src[v];
            int k = v >> 1, half = v & 1;
            float* row = s + k * 9 + half * 4;
            row[0] = d.x; row[1] = d.y; row[2] = d.z; row[3] = d.w;
        }
        const float pbj = Pb[j];
        __syncthreads();
        #pragma unroll
        for (int u = 0; u < 16; ++u) {
            int e = tid + u * 256;           // e = x*512 + k
            int x = e >> 9, k = e & 511;
            float val = s[k * 9 + x] * pbj * Pc[k];
            g_Ahf[((size_t)(j * 8 + x)) * 512 + k] = __float2half_rn(val);
        }
    } else {
        const int i = bid - 512;
        #pragma unroll
        for (int u = 0; u < 4; ++u) {
            int v = tid + u * 256;
            int k = v >> 1, half = v & 1;
            float4 d = *(const float4*)(B + (size_t)k * 4096 + i * 8 + half * 4);
            float* row = s + k * 9 + half * 4;
            row[0] = d.x; row[1] = d.y; row[2] = d.z; row[3] = d.w;
        }
        const float pai = Pa[i];
        __syncthreads();
        #pragma unroll
        for (int u = 0; u < 16; ++u) {
            int e = tid + u * 256;           // e = y*512 + k
            int y = e >> 9, k = e & 511;
            float val = s[k * 9 + y] * pai;
            g_Bhf[((size_t)(i * 8 + y)) * 512 + k] = __float2half_rn(val);
        }
    }
}

// ============================================================================
// Kernel 2: GEMM, CTA tile 128x128, 4 warps (warp tile 64x64, 2m x 2n),
//           split-K=1: K=512 in 8 chunks of 64, 2-buffer ping-pong,
//           fp16 acc, fused epilogue + KL finalize.
// grid 1024 = ntile(32) x mtile(32); 128 threads; 3 CTAs/SM.
// ============================================================================
static constexpr int CHUNK = 16384;             // 128 rows * 128B (A or B)
static constexpr int OFF_B0 = 2 * CHUNK;        // A stages 0,1; B stages 2,3
static constexpr int OFF_C  = 4 * CHUNK;        // C tile 16*16*8 f = 8 KB
static constexpr int SMEM_USED = OFF_C + 8192;  // 73728 B
static constexpr int GEMM_SMEM = SMEM_USED + 1024; // 74752 B (x3 = 219 KB/SM)

__global__ void __launch_bounds__(128, 3) gemm_kernel(const float* __restrict__ y_pred,
                                                      const float* __restrict__ y_true,
                                                      float* __restrict__ out,
                                                      int out_size) {
    extern __shared__ char smem_raw[];
    char* dyn = (char*)((((uintptr_t)smem_raw) + 1023) & ~(uintptr_t)1023);
    const uint32_t dbase = smem_u32(dyn);

    __shared__ float s_probs[512];
    __shared__ unsigned s_last;
    __shared__ float red[4];

    const int tid = threadIdx.x;
    const int wid = tid >> 5;
    const int lid = tid & 31;
    const int wm = wid & 1;          // m block of 64
    const int wn = wid >> 1;         // n block of 64 (0..1)
    const int mtile = blockIdx.x & 31;
    const int ntile = blockIdx.x >> 5;
    const int m0 = mtile * 128;
    const int n0 = ntile * 128;

    #pragma unroll
    for (int q = 0; q < 4; ++q) s_probs[tid + q * 128] = 0.0f;

    // ---- per-thread swizzled prefetch bases (+2048B steps are SW128-invariant)
    const int prow = tid >> 3, pc16 = tid & 7;       // prow 0..15
    const uint32_t dA0 = dbase + SWZ128((uint32_t)(prow * 128 + pc16 * 16));
    const uint32_t dB0 = dA0 + (uint32_t)OFF_B0;
    const __half* sA0 = g_Ahf + ((size_t)(m0 + prow)) * 512 + pc16 * 8;
    const __half* sB0 = g_Bhf + ((size_t)(n0 + prow)) * 512 + pc16 * 8;

    // ---- prefetch chunks 0 (buf0) and 1 (buf1): G0, G1 ----
    #pragma unroll
    for (int c = 0; c < 2; ++c) {
        #pragma unroll
        for (int t = 0; t < 8; ++t)       // A rows: prow + 16t
            cp_async16(dA0 + c * CHUNK + t * 2048,
                       sA0 + c * 64 + (size_t)t * 16 * 512);
        #pragma unroll
        for (int t = 0; t < 8; ++t)       // B rows: prow + 16t
            cp_async16(dB0 + c * CHUNK + t * 2048,
                       sB0 + c * 64 + (size_t)t * 16 * 512);
        CP_COMMIT();
    }

    // ---- load C tile (plain LDG, overlaps cp.async): Cs[i_local][j_local][z] ----
    {
        const float* Cg = y_pred + 1536 + 2ull * 512 * 4096;
        const int i0 = ntile * 16, j0 = mtile * 16;
        float* Cs = (float*)(dyn + OFF_C);
        #pragma unroll
        for (int u = 0; u < 4; ++u) {
            int idx = tid + u * 128;          // 512 float4
            int ii = idx >> 5, rem = idx & 31;
            int jj = rem >> 1, half = rem & 1;
            float4 d = *(const float4*)(Cg + (((size_t)(i0 + ii) * 512 + (j0 + jj)) * 8 + half * 4));
            *(float4*)(Cs + ((ii * 16 + jj) * 8 + half * 4)) = d;
        }
    }

    // ---- lane-fixed fragment geometry (warp tile 64x64) ----
    const int sub = lid >> 3, rowin = lid & 7;
    const int a_row = wm * 64 + (sub & 1) * 8 + rowin;   // + mf*16, mf<4
    const int b_row = wn * 64 + (sub & 1) * 8 + rowin;   // + nb*8,  nb<8
    const int ksub  = (sub >> 1) * 8;                    // + ks*16

    uint32_t acc[4][8][2];                   // fp16x2 accumulators (64 regs)
    #pragma unroll
    for (int mf = 0; mf < 4; ++mf)
        #pragma unroll
        for (int nf = 0; nf < 8; ++nf) { acc[mf][nf][0] = 0u; acc[mf][nf][1] = 0u; }

    // ---- K loop: 8 chunks of 64, 2-buffer ping-pong.
    //      Ledger at iter c: pending {Gc, G(c+1)} -> WAIT(1) retires Gc
    //      (WAIT(0) at c=7). Second barrier retires all reads of buf before
    //      the c+2 prefetch overwrites it. Barriers hidden by 3 CTAs/SM.
    #pragma unroll 1
    for (int c = 0; c < 8; ++c) {
        if (c < 7) { CP_WAIT(1); } else { CP_WAIT(0); }
        __syncthreads();

        const int b = c & 1;
        const uint32_t abuf = dbase + b * CHUNK;
        const uint32_t bbuf = dbase + OFF_B0 + b * CHUNK;

        #pragma unroll
        for (int ks = 0; ks < 4; ++ks) {
            uint32_t afr[4][4];
            #pragma unroll
            for (int mf = 0; mf < 4; ++mf)
                ldmatrix_x4(abuf + SWZ128((uint32_t)((a_row + mf * 16) * 128 + (ks * 16 + ksub) * 2)),
                            afr[mf][0], afr[mf][1], afr[mf][2], afr[mf][3]);
            uint32_t b0[8], b1[8];
            #pragma unroll
            for (int nb = 0; nb < 8; nb += 2) {
                uint32_t r0, r1, r2, r3;
                ldmatrix_x4(bbuf + SWZ128((uint32_t)((b_row + nb * 8) * 128 + (ks * 16 + ksub) * 2)),
                            r0, r1, r2, r3);
                b0[nb] = r0; b0[nb + 1] = r1; b1[nb] = r2; b1[nb + 1] = r3;
            }
            #pragma unroll
            for (int mf = 0; mf < 4; ++mf)
                #pragma unroll
                for (int nf = 0; nf < 8; ++nf)
                    mma16816_f16(acc[mf][nf], afr[mf], b0[nf], b1[nf]);
        }
        __syncthreads();                     // buf reads retired

        if (c < 6) {                         // prefetch chunk c+2 into buf b
            const int kb = (c + 2) * 64;
            #pragma unroll
            for (int t = 0; t < 8; ++t)
                cp_async16(dA0 + b * CHUNK + t * 2048,
                           sA0 + kb + (size_t)t * 16 * 512);
            #pragma unroll
            for (int t = 0; t < 8; ++t)
                cp_async16(dB0 + b * CHUNK + t * 2048,
                           sB0 + kb + (size_t)t * 16 * 512);
            CP_COMMIT();
        }
    }

    // ---- fused epilogue: probs[x,y,z] += D * C ----
    // x = lid>>2; y-pair cc; j_local = wm*8+mf*2+rp; i_local = wn*8+nf
    {
        const float* Cs = (const float*)(dyn + OFF_C);
        float partial[2][8];
        #pragma unroll
        for (int cc = 0; cc < 2; ++cc)
            #pragma unroll
            for (int z = 0; z < 8; ++z) partial[cc][z] = 0.0f;

        #pragma unroll
        for (int mf = 0; mf < 4; ++mf)
            #pragma unroll
            for (int rp = 0; rp < 2; ++rp) {
                const int j = wm * 8 + mf * 2 + rp;
                #pragma unroll
                for (int nf = 0; nf < 8; ++nf) {
                    const int i = wn * 8 + nf;
                    const float* cp = Cs + ((i * 16 + j) * 8);
                    float4 cA = *(const float4*)cp;
                    float4 cB = *(const float4*)(cp + 4);
                    const __half2 h = *(const __half2*)&acc[mf][nf][rp];
                    const float vlo = __low2float(h);    // col cc=0
                    const float vhi = __high2float(h);   // col cc=1
                    partial[0][0] = fmaf(vlo, cA.x, partial[0][0]);
                    partial[0][1] = fmaf(vlo, cA.y, partial[0][1]);
                    partial[0][2] = fmaf(vlo, cA.z, partial[0][2]);
                    partial[0][3] = fmaf(vlo, cA.w, partial[0][3]);
                    partial[0][4] = fmaf(vlo, cB.x, partial[0][4]);
                    partial[0][5] = fmaf(vlo, cB.y, partial[0][5]);
                    partial[0][6] = fmaf(vlo, cB.z, partial[0][6]);
                    partial[0][7] = fmaf(vlo, cB.w, partial[0][7]);
                    partial[1][0] = fmaf(vhi, cA.x, partial[1][0]);
                    partial[1][1] = fmaf(vhi, cA.y, partial[1][1]);
                    partial[1][2] = fmaf(vhi, cA.z, partial[1][2]);
                    partial[1][3] = fmaf(vhi, cA.w, partial[1][3]);
                    partial[1][4] = fmaf(vhi, cB.x, partial[1][4]);
                    partial[1][5] = fmaf(vhi, cB.y, partial[1][5]);
                    partial[1][6] = fmaf(vhi, cB.z, partial[1][6]);
                    partial[1][7] = fmaf(vhi, cB.w, partial[1][7]);
                }
            }

        const int x = lid >> 2;
        const int ybase = 2 * (lid & 3);
        #pragma unroll
        for (int cc = 0; cc < 2; ++cc)
            #pragma unroll
            for (int z = 0; z < 8; ++z)
                atomicAdd(&s_probs[x * 64 + (ybase + cc) * 8 + z], partial[cc][z]);
    }
    __syncthreads();

    #pragma unroll
    for (int q = 0; q < 4; ++q)
        atomicAdd(&g_probs[tid + q * 128], s_probs[tid + q * 128]);

    // ---- last-block fused finalize: KL divergence + emit (d, probs) ----
    __threadfence();
    if (tid == 0) s_last = atomicAdd(&g_ctr, 1u);
    __syncthreads();
    if (s_last == (unsigned)(gridDim.x - 1)) {
        __threadfence();
        float p[4], term = 0.0f;
        #pragma unroll
        for (int q = 0; q < 4; ++q) {
            p[q] = g_probs[tid + q * 128];
            const float pc = fminf(fmaxf(p[q], 1e-10f), 1.0f);
            const float yt = y_true[tid + q * 128];
            term += yt * (logf(yt + 1e-10f) - logf(pc));
        }

        #pragma unroll
        for (int o = 16; o; o >>= 1) term += __shfl_xor_sync(0xFFFFFFFFu, term, o);
        if (lid == 0) red[wid] = term;
        __syncthreads();

        float d = 0.0f;
        if (tid < 4) {
            float v = red[tid];
            v += __shfl_xor_sync(0xFu, v, 2);
            v += __shfl_xor_sync(0xFu, v, 1);
            d = v;
        }

        if (out_size >= 513) {
            if (tid == 0) out[0] = d;
            #pragma unroll
            for (int q = 0; q < 4; ++q) out[1 + tid + q * 128] = p[q];
        } else if (out_size == 512) {
            #pragma unroll
            for (int q = 0; q < 4; ++q) out[tid + q * 128] = p[q];
        } else if (out_size >= 1) {
            if (tid == 0) out[0] = d;
        }
    }
}

// ============================================================================
extern "C" void kernel_launch(void* const* d_in, const int* in_sizes, int n_in,
                              void* d_out, int out_size) {
    const float* y_pred = (const float*)d_in[0];
    const float* y_true = (const float*)d_in[1];
    float* out = (float*)d_out;

    cudaFuncSetAttribute(gemm_kernel,
                         cudaFuncAttributeMaxDynamicSharedMemorySize, GEMM_SMEM);

    conv_kernel<<<1024, 256>>>(y_pred);
    gemm_kernel<<<1024, 128, GEMM_SMEM>>>(y_pred, y_true, out, out_size);
}

// round 14
// speedup vs baseline: 1.7014x; 1.7014x over previous
#include <cuda_runtime.h>
#include <cuda_fp16.h>
#include <cstdint>

// ============================================================================
// probs[x,y,z] = sum_{i,j,k} A[j,k,x]Pb[j]Pc[k] * B[k,i,y]Pa[i] * C[i,j,z]
// K=512, O=8.
//  1) conv:  Ahf[j*8+x,k] = fp16(A[j,k,x]*Pb[j]*Pc[k])
//            Bhf[i*8+y,k] = fp16(B[k,i,y]*Pa[i])
//  2) gemm:  D[m,n] = sum_k Ahf[m,k]*Bhf[n,k]  (4096x4096x512, mma.sync fp16
//            acc). CTA tile 128x128, 4 warps (warp tile 64x64), split-K=1,
//            K=512 in 8 chunks of 64, 2-buffer ping-pong, 3 CTAs/SM
//            (s_probs aliased into dynamic smem so 3 CTAs FIT), algebraic
//            swizzle hoist (addresses = base + const, no runtime LOP3),
//            fused epilogue probs += D*C, fused last-block KL finalize.
// ============================================================================

__device__ __half g_Ahf[4096ull * 512];
__device__ __half g_Bhf[4096ull * 512];
__device__ float g_probs[512];
__device__ unsigned g_ctr;

__device__ __forceinline__ uint32_t smem_u32(const void* p) {
    uint32_t a;
    asm("{ .reg .u64 t; cvta.to.shared.u64 t, %1; cvt.u32.u64 %0, t; }" : "=r"(a) : "l"(p));
    return a;
}

#define SWZ128(off) ((off) ^ (((off) >> 3) & 0x70))

__device__ __forceinline__ void ldmatrix_x4(uint32_t addr, uint32_t& r0, uint32_t& r1,
                                            uint32_t& r2, uint32_t& r3) {
    asm volatile("ldmatrix.sync.aligned.m8n8.x4.shared.b16 {%0,%1,%2,%3}, [%4];"
                 : "=r"(r0), "=r"(r1), "=r"(r2), "=r"(r3) : "r"(addr));
}

// fp16-accumulate MMA: D(2xb32 = 4 halves) += A(4xb32) * B(2xb32)
__device__ __forceinline__ void mma16816_f16(uint32_t* d, const uint32_t* a,
                                             uint32_t b0, uint32_t b1) {
    asm volatile(
        "mma.sync.aligned.m16n8k16.row.col.f16.f16.f16.f16 "
        "{%0,%1}, {%2,%3,%4,%5}, {%6,%7}, {%0,%1};"
        : "+r"(d[0]), "+r"(d[1])
        : "r"(a[0]), "r"(a[1]), "r"(a[2]), "r"(a[3]), "r"(b0), "r"(b1));
}

__device__ __forceinline__ void cp_async16(uint32_t dst, const void* src) {
    asm volatile("cp.async.cg.shared.global [%0], [%1], 16;"
                 :: "r"(dst), "l"(src) : "memory");
}
#define CP_COMMIT() asm volatile("cp.async.commit_group;" ::: "memory")
#define CP_WAIT(n)  asm volatile("cp.async.wait_group %0;" :: "n"(n) : "memory")

// ============================================================================
// Kernel 1: fold scales + transpose + convert to fp16 K-major operands.
// ============================================================================
__global__ void __launch_bounds__(256) conv_kernel(const float* __restrict__ y_pred) {
    __shared__ float s[512 * 9];   // k-major, stride 9 (conflict-free transpose)
    const int tid = threadIdx.x;
    const int bid = blockIdx.x;

    if (bid == 0) {
        for (int i = tid; i < 512; i += 256) g_probs[i] = 0.0f;
        if (tid == 0) g_ctr = 0;
    }

    const float* Pa = y_pred;
    const float* Pb = y_pred + 512;
    const float* Pc = y_pred + 1024;
    const float* A  = y_pred + 1536;
    const float* B  = A + 512ull * 4096;

    if (bid < 512) {
        const int j = bid;
        const float4* src = (const float4*)(A + (size_t)j * 4096);
        #pragma unroll
        for (int u = 0; u < 4; ++u) {
            int v = tid + u * 256;           // 1024 float4 = 4096 floats (k,x)
            float4 d = src[v];
            int k = v >> 1, half = v & 1;
            float* row = s + k * 9 + half * 4;
            row[0] = d.x; row[1] = d.y; row[2] = d.z; row[3] = d.w;
        }
        const float pbj = Pb[j];
        __syncthreads();
        #pragma unroll
        for (int u = 0; u < 16; ++u) {
            int e = tid + u * 256;           // e = x*512 + k
            int x = e >> 9, k = e & 511;
            float val = s[k * 9 + x] * pbj * Pc[k];
            g_Ahf[((size_t)(j * 8 + x)) * 512 + k] = __float2half_rn(val);
        }
    } else {
        const int i = bid - 512;
        #pragma unroll
        for (int u = 0; u < 4; ++u) {
            int v = tid + u * 256;
            int k = v >> 1, half = v & 1;
            float4 d = *(const float4*)(B + (size_t)k * 4096 + i * 8 + half * 4);
            float* row = s + k * 9 + half * 4;
            row[0] = d.x; row[1] = d.y; row[2] = d.z; row[3] = d.w;
        }
        const float pai = Pa[i];
        __syncthreads();
        #pragma unroll
        for (int u = 0; u < 16; ++u) {
            int e = tid + u * 256;           // e = y*512 + k
            int y = e >> 9, k = e & 511;
            float val = s[k * 9 + y] * pai;
            g_Bhf[((size_t)(i * 8 + y)) * 512 + k] = __float2half_rn(val);
        }
    }
}

// ============================================================================
// Kernel 2: GEMM, CTA tile 128x128, 4 warps (warp tile 64x64, 2m x 2n),
//           split-K=1: K=512 in 8 chunks of 64, 2-buffer ping-pong,
//           fp16 acc, fused epilogue + KL finalize. 3 CTAs/SM.
// grid 1024 = ntile(32) x mtile(32); 128 threads.
// ============================================================================
static constexpr int CHUNK = 16384;             // 128 rows * 128B (A or B)
static constexpr int OFF_B0 = 2 * CHUNK;        // A stages 0,1; B stages 2,3
static constexpr int OFF_C  = 4 * CHUNK;        // C tile 16*16*8 f = 8 KB
static constexpr int SMEM_USED = OFF_C + 8192;  // 73728 B
static constexpr int GEMM_SMEM = SMEM_USED + 1024; // 74752 B (x3 = 224.3 KB/SM)

__global__ void __launch_bounds__(128, 3) gemm_kernel(const float* __restrict__ y_pred,
                                                      const float* __restrict__ y_true,
                                                      float* __restrict__ out,
                                                      int out_size) {
    extern __shared__ char smem_raw[];
    char* dyn = (char*)((((uintptr_t)smem_raw) + 1023) & ~(uintptr_t)1023);
    const uint32_t dbase = smem_u32(dyn);

    __shared__ unsigned s_last;
    __shared__ float red[4];

    const int tid = threadIdx.x;
    const int wid = tid >> 5;
    const int lid = tid & 31;
    const int wm = wid & 1;          // m block of 64
    const int wn = wid >> 1;         // n block of 64 (0..1)
    const int mtile = blockIdx.x & 31;
    const int ntile = blockIdx.x >> 5;
    const int m0 = mtile * 128;
    const int n0 = ntile * 128;

    // ---- per-thread swizzled prefetch bases (+2048B steps are SW128-invariant)
    const int prow = tid >> 3, pc16 = tid & 7;       // prow 0..15
    const uint32_t dA0 = dbase + SWZ128((uint32_t)(prow * 128 + pc16 * 16));
    const uint32_t dB0 = dA0 + (uint32_t)OFF_B0;
    const __half* sA0 = g_Ahf + ((size_t)(m0 + prow)) * 512 + pc16 * 8;
    const __half* sB0 = g_Bhf + ((size_t)(n0 + prow)) * 512 + pc16 * 8;

    // ---- prefetch chunks 0 (buf0) and 1 (buf1): G0, G1 ----
    #pragma unroll
    for (int c = 0; c < 2; ++c) {
        #pragma unroll
        for (int t = 0; t < 8; ++t)       // A rows: prow + 16t
            cp_async16(dA0 + c * CHUNK + t * 2048,
                       sA0 + c * 64 + (size_t)t * 16 * 512);
        #pragma unroll
        for (int t = 0; t < 8; ++t)       // B rows: prow + 16t
            cp_async16(dB0 + c * CHUNK + t * 2048,
                       sB0 + c * 64 + (size_t)t * 16 * 512);
        CP_COMMIT();
    }

    // ---- load C tile (plain LDG, overlaps cp.async): Cs[i_local][j_local][z] ----
    {
        const float* Cg = y_pred + 1536 + 2ull * 512 * 4096;
        const int i0 = ntile * 16, j0 = mtile * 16;
        float* Cs = (float*)(dyn + OFF_C);
        #pragma unroll
        for (int u = 0; u < 4; ++u) {
            int idx = tid + u * 128;          // 512 float4
            int ii = idx >> 5, rem = idx & 31;
            int jj = rem >> 1, half = rem & 1;
            float4 d = *(const float4*)(Cg + (((size_t)(i0 + ii) * 512 + (j0 + jj)) * 8 + half * 4));
            *(float4*)(Cs + ((ii * 16 + jj) * 8 + half * 4)) = d;
        }
    }

    // ---- lane-fixed fragment geometry (warp tile 64x64) ----
    // Algebraic swizzle hoist: for x = row*128 + c (c < 128),
    //   SWZ128(x) = row*128 + (c ^ ((row&7)<<4)),
    // and row&7 == rowin for ALL fragment rows (offsets are multiples of 8).
    const int sub = lid >> 3, rowin = lid & 7;
    const int a_row = wm * 64 + (sub & 1) * 8 + rowin;   // + mf*16, mf<4
    const int b_row = wn * 64 + (sub & 1) * 8 + rowin;   // + nb*8,  nb<8
    const int ksub  = (sub >> 1) * 8;                    // + ks*16
    const uint32_t xm = (uint32_t)(rowin << 4);
    uint32_t csw[4];
    #pragma unroll
    for (int ks = 0; ks < 4; ++ks)
        csw[ks] = ((uint32_t)((ks * 16 + ksub) * 2)) ^ xm;
    const uint32_t aoff0 = (uint32_t)(a_row * 128);
    const uint32_t boff0 = (uint32_t)(b_row * 128);

    uint32_t acc[4][8][2];                   // fp16x2 accumulators (64 regs)
    #pragma unroll
    for (int mf = 0; mf < 4; ++mf)
        #pragma unroll
        for (int nf = 0; nf < 8; ++nf) { acc[mf][nf][0] = 0u; acc[mf][nf][1] = 0u; }

    // ---- K loop: 8 chunks of 64, 2-buffer ping-pong.
    //      Pending {Gc, G(c+1)} -> WAIT(1) retires Gc (WAIT(0) at c=7).
    //      Second barrier retires buf reads before the c+2 prefetch overwrites.
    #pragma unroll 1
    for (int c = 0; c < 8; ++c) {
        if (c < 7) { CP_WAIT(1); } else { CP_WAIT(0); }
        __syncthreads();

        const int b = c & 1;
        const uint32_t abuf = dbase + b * CHUNK + aoff0;
        const uint32_t bbuf = dbase + OFF_B0 + b * CHUNK + boff0;

        #pragma unroll
        for (int ks = 0; ks < 4; ++ks) {
            const uint32_t cs = csw[ks];
            uint32_t afr[4][4];
            #pragma unroll
            for (int mf = 0; mf < 4; ++mf)
                ldmatrix_x4(abuf + (uint32_t)(mf * 2048) + cs,
                            afr[mf][0], afr[mf][1], afr[mf][2], afr[mf][3]);
            uint32_t b0[8], b1[8];
            #pragma unroll
            for (int nb = 0; nb < 8; nb += 2) {
                uint32_t r0, r1, r2, r3;
                ldmatrix_x4(bbuf + (uint32_t)(nb * 1024) + cs, r0, r1, r2, r3);
                b0[nb] = r0; b0[nb + 1] = r1; b1[nb] = r2; b1[nb + 1] = r3;
            }
            #pragma unroll
            for (int mf = 0; mf < 4; ++mf)
                #pragma unroll
                for (int nf = 0; nf < 8; ++nf)
                    mma16816_f16(acc[mf][nf], afr[mf], b0[nf], b1[nf]);
        }
        __syncthreads();                     // buf reads retired

        if (c < 6) {                         // prefetch chunk c+2 into buf b
            const int kb = (c + 2) * 64;
            #pragma unroll
            for (int t = 0; t < 8; ++t)
                cp_async16(dA0 + b * CHUNK + t * 2048,
                           sA0 + kb + (size_t)t * 16 * 512);
            #pragma unroll
            for (int t = 0; t < 8; ++t)
                cp_async16(dB0 + b * CHUNK + t * 2048,
                           sB0 + kb + (size_t)t * 16 * 512);
            CP_COMMIT();
        }
    }

    // ---- s_probs lives in dynamic smem, aliased over the (dead) A/B buffers ----
    float* sp = (float*)dyn;                 // 512 floats at offset 0
    #pragma unroll
    for (int q = 0; q < 4; ++q) sp[tid + q * 128] = 0.0f;
    __syncthreads();

    // ---- fused epilogue: probs[x,y,z] += D * C ----
    // x = lid>>2; y-pair cc; j_local = wm*8+mf*2+rp; i_local = wn*8+nf
    {
        const float* Cs = (const float*)(dyn + OFF_C);
        float partial[2][8];
        #pragma unroll
        for (int cc = 0; cc < 2; ++cc)
            #pragma unroll
            for (int z = 0; z < 8; ++z) partial[cc][z] = 0.0f;

        #pragma unroll
        for (int mf = 0; mf < 4; ++mf)
            #pragma unroll
            for (int rp = 0; rp < 2; ++rp) {
                const int j = wm * 8 + mf * 2 + rp;
                #pragma unroll
                for (int nf = 0; nf < 8; ++nf) {
                    const int i = wn * 8 + nf;
                    const float* cp = Cs + ((i * 16 + j) * 8);
                    float4 cA = *(const float4*)cp;
                    float4 cB = *(const float4*)(cp + 4);
                    const __half2 h = *(const __half2*)&acc[mf][nf][rp];
                    const float vlo = __low2float(h);    // col cc=0
                    const float vhi = __high2float(h);   // col cc=1
                    partial[0][0] = fmaf(vlo, cA.x, partial[0][0]);
                    partial[0][1] = fmaf(vlo, cA.y, partial[0][1]);
                    partial[0][2] = fmaf(vlo, cA.z, partial[0][2]);
                    partial[0][3] = fmaf(vlo, cA.w, partial[0][3]);
                    partial[0][4] = fmaf(vlo, cB.x, partial[0][4]);
                    partial[0][5] = fmaf(vlo, cB.y, partial[0][5]);
                    partial[0][6] = fmaf(vlo, cB.z, partial[0][6]);
                    partial[0][7] = fmaf(vlo, cB.w, partial[0][7]);
                    partial[1][0] = fmaf(vhi, cA.x, partial[1][0]);
                    partial[1][1] = fmaf(vhi, cA.y, partial[1][1]);
                    partial[1][2] = fmaf(vhi, cA.z, partial[1][2]);
                    partial[1][3] = fmaf(vhi, cA.w, partial[1][3]);
                    partial[1][4] = fmaf(vhi, cB.x, partial[1][4]);
                    partial[1][5] = fmaf(vhi, cB.y, partial[1][5]);
                    partial[1][6] = fmaf(vhi, cB.z, partial[1][6]);
                    partial[1][7] = fmaf(vhi, cB.w, partial[1][7]);
                }
            }

        const int x = lid >> 2;
        const int ybase = 2 * (lid & 3);
        #pragma unroll
        for (int cc = 0; cc < 2; ++cc)
            #pragma unroll
            for (int z = 0; z < 8; ++z)
                atomicAdd(&sp[x * 64 + (ybase + cc) * 8 + z], partial[cc][z]);
    }
    __syncthreads();

    #pragma unroll
    for (int q = 0; q < 4; ++q)
        atomicAdd(&g_probs[tid + q * 128], sp[tid + q * 128]);

    // ---- last-block fused finalize: KL divergence + emit (d, probs) ----
    __threadfence();
    if (tid == 0) s_last = atomicAdd(&g_ctr, 1u);
    __syncthreads();
    if (s_last == (unsigned)(gridDim.x - 1)) {
        __threadfence();
        float p[4], term = 0.0f;
        #pragma unroll
        for (int q = 0; q < 4; ++q) {
            p[q] = g_probs[tid + q * 128];
            const float pc = fminf(fmaxf(p[q], 1e-10f), 1.0f);
            const float yt = y_true[tid + q * 128];
            term += yt * (logf(yt + 1e-10f) - logf(pc));
        }

        #pragma unroll
        for (int o = 16; o; o >>= 1) term += __shfl_xor_sync(0xFFFFFFFFu, term, o);
        if (lid == 0) red[wid] = term;
        __syncthreads();

        float d = 0.0f;
        if (tid < 4) {
            float v = red[tid];
            v += __shfl_xor_sync(0xFu, v, 2);
            v += __shfl_xor_sync(0xFu, v, 1);
            d = v;
        }

        if (out_size >= 513) {
            if (tid == 0) out[0] = d;
            #pragma unroll
            for (int q = 0; q < 4; ++q) out[1 + tid + q * 128] = p[q];
        } else if (out_size == 512) {
            #pragma unroll
            for (int q = 0; q < 4; ++q) out[tid + q * 128] = p[q];
        } else if (out_size >= 1) {
            if (tid == 0) out[0] = d;
        }
    }
}

// ============================================================================
extern "C" void kernel_launch(void* const* d_in, const int* in_sizes, int n_in,
                              void* d_out, int out_size) {
    const float* y_pred = (const float*)d_in[0];
    const float* y_true = (const float*)d_in[1];
    float* out = (float*)d_out;

    cudaFuncSetAttribute(gemm_kernel,
                         cudaFuncAttributeMaxDynamicSharedMemorySize, GEMM_SMEM);

    conv_kernel<<<1024, 256>>>(y_pred);
    gemm_kernel<<<1024, 128, GEMM_SMEM>>>(y_pred, y_true, out, out_size);
}

// round 15
// speedup vs baseline: 1.7179x; 1.0097x over previous
#include <cuda_runtime.h>
#include <cuda_fp16.h>
#include <cstdint>

// ============================================================================
// probs[x,y,z] = sum_{i,j,k} A[j,k,x]Pb[j]Pc[k] * B[k,i,y]Pa[i] * C[i,j,z]
// K=512, O=8.
//  1) conv:  Ahf[j*8+x,k] = fp16(A[j,k,x]*Pb[j]*Pc[k])
//            Bhf[i*8+y,k] = fp16(B[k,i,y]*Pa[i])
//  2) gemm:  D[m,n] = sum_k Ahf[m,k]*Bhf[n,k]  (4096x4096x512, mma.sync fp16
//            acc). CTA tile 128x128, 4 warps (warp tile 64x64), split-K=1,
//            K=512 in 8 chunks of 64, 2-buffer ping-pong, 3 CTAs/SM
//            (s_probs aliased into dynamic smem so 3 CTAs FIT), algebraic
//            swizzle hoist (addresses = base + const, no runtime LOP3),
//            fused epilogue probs += D*C, fused last-block KL finalize.
// ============================================================================

__device__ __half g_Ahf[4096ull * 512];
__device__ __half g_Bhf[4096ull * 512];
__device__ float g_probs[512];
__device__ unsigned g_ctr;

__device__ __forceinline__ uint32_t smem_u32(const void* p) {
    uint32_t a;
    asm("{ .reg .u64 t; cvta.to.shared.u64 t, %1; cvt.u32.u64 %0, t; }" : "=r"(a) : "l"(p));
    return a;
}

#define SWZ128(off) ((off) ^ (((off) >> 3) & 0x70))

__device__ __forceinline__ void ldmatrix_x4(uint32_t addr, uint32_t& r0, uint32_t& r1,
                                            uint32_t& r2, uint32_t& r3) {
    asm volatile("ldmatrix.sync.aligned.m8n8.x4.shared.b16 {%0,%1,%2,%3}, [%4];"
                 : "=r"(r0), "=r"(r1), "=r"(r2), "=r"(r3) : "r"(addr));
}

// fp16-accumulate MMA: D(2xb32 = 4 halves) += A(4xb32) * B(2xb32)
__device__ __forceinline__ void mma16816_f16(uint32_t* d, const uint32_t* a,
                                             uint32_t b0, uint32_t b1) {
    asm volatile(
        "mma.sync.aligned.m16n8k16.row.col.f16.f16.f16.f16 "
        "{%0,%1}, {%2,%3,%4,%5}, {%6,%7}, {%0,%1};"
        : "+r"(d[0]), "+r"(d[1])
        : "r"(a[0]), "r"(a[1]), "r"(a[2]), "r"(a[3]), "r"(b0), "r"(b1));
}

__device__ __forceinline__ void cp_async16(uint32_t dst, const void* src) {
    asm volatile("cp.async.cg.shared.global [%0], [%1], 16;"
                 :: "r"(dst), "l"(src) : "memory");
}
#define CP_COMMIT() asm volatile("cp.async.commit_group;" ::: "memory")
#define CP_WAIT(n)  asm volatile("cp.async.wait_group %0;" :: "n"(n) : "memory")

// ============================================================================
// Kernel 1: fold scales + transpose + convert to fp16 K-major operands.
// ============================================================================
__global__ void __launch_bounds__(256) conv_kernel(const float* __restrict__ y_pred) {
    __shared__ float s[512 * 9];   // k-major, stride 9 (conflict-free transpose)
    const int tid = threadIdx.x;
    const int bid = blockIdx.x;

    if (bid == 0) {
        for (int i = tid; i < 512; i += 256) g_probs[i] = 0.0f;
        if (tid == 0) g_ctr = 0;
    }

    const float* Pa = y_pred;
    const float* Pb = y_pred + 512;
    const float* Pc = y_pred + 1024;
    const float* A  = y_pred + 1536;
    const float* B  = A + 512ull * 4096;

    if (bid < 512) {
        const int j = bid;
        const float4* src = (const float4*)(A + (size_t)j * 4096);
        #pragma unroll
        for (int u = 0; u < 4; ++u) {
            int v = tid + u * 256;           // 1024 float4 = 4096 floats (k,x)
            float4 d = src[v];
            int k = v >> 1, half = v & 1;
            float* row = s + k * 9 + half * 4;
            row[0] = d.x; row[1] = d.y; row[2] = d.z; row[3] = d.w;
        }
        const float pbj = Pb[j];
        __syncthreads();
        #pragma unroll
        for (int u = 0; u < 16; ++u) {
            int e = tid + u * 256;           // e = x*512 + k
            int x = e >> 9, k = e & 511;
            float val = s[k * 9 + x] * pbj * Pc[k];
            g_Ahf[((size_t)(j * 8 + x)) * 512 + k] = __float2half_rn(val);
        }
    } else {
        const int i = bid - 512;
        #pragma unroll
        for (int u = 0; u < 4; ++u) {
            int v = tid + u * 256;
            int k = v >> 1, half = v & 1;
            float4 d = *(const float4*)(B + (size_t)k * 4096 + i * 8 + half * 4);
            float* row = s + k * 9 + half * 4;
            row[0] = d.x; row[1] = d.y; row[2] = d.z; row[3] = d.w;
        }
        const float pai = Pa[i];
        __syncthreads();
        #pragma unroll
        for (int u = 0; u < 16; ++u) {
            int e = tid + u * 256;           // e = y*512 + k
            int y = e >> 9, k = e & 511;
            float val = s[k * 9 + y] * pai;
            g_Bhf[((size_t)(i * 8 + y)) * 512 + k] = __float2half_rn(val);
        }
    }
}

// ============================================================================
// Kernel 2: GEMM, CTA tile 128x128, 4 warps (warp tile 64x64, 2m x 2n),
//           split-K=1: K=512 in 8 chunks of 64, 2-buffer ping-pong,
//           fp16 acc, fused epilogue + KL finalize. 3 CTAs/SM.
// grid 1024 = ntile(32) x mtile(32); 128 threads.
// ============================================================================
static constexpr int CHUNK = 16384;             // 128 rows * 128B (A or B)
static constexpr int OFF_B0 = 2 * CHUNK;        // A stages 0,1; B stages 2,3
static constexpr int OFF_C  = 4 * CHUNK;        // C tile 16*16*8 f = 8 KB
static constexpr int SMEM_USED = OFF_C + 8192;  // 73728 B
static constexpr int GEMM_SMEM = SMEM_USED + 1024; // 74752 B (x3 = 224.3 KB/SM)

__global__ void __launch_bounds__(128, 3) gemm_kernel(const float* __restrict__ y_pred,
                                                      const float* __restrict__ y_true,
                                                      float* __restrict__ out,
                                                      int out_size) {
    extern __shared__ char smem_raw[];
    char* dyn = (char*)((((uintptr_t)smem_raw) + 1023) & ~(uintptr_t)1023);
    const uint32_t dbase = smem_u32(dyn);

    __shared__ unsigned s_last;
    __shared__ float red[4];

    const int tid = threadIdx.x;
    const int wid = tid >> 5;
    const int lid = tid & 31;
    const int wm = wid & 1;          // m block of 64
    const int wn = wid >> 1;         // n block of 64 (0..1)
    const int mtile = blockIdx.x & 31;
    const int ntile = blockIdx.x >> 5;
    const int m0 = mtile * 128;
    const int n0 = ntile * 128;

    // ---- per-thread swizzled prefetch bases (+2048B steps are SW128-invariant)
    const int prow = tid >> 3, pc16 = tid & 7;       // prow 0..15
    const uint32_t dA0 = dbase + SWZ128((uint32_t)(prow * 128 + pc16 * 16));
    const uint32_t dB0 = dA0 + (uint32_t)OFF_B0;
    const __half* sA0 = g_Ahf + ((size_t)(m0 + prow)) * 512 + pc16 * 8;
    const __half* sB0 = g_Bhf + ((size_t)(n0 + prow)) * 512 + pc16 * 8;

    // ---- prefetch chunks 0 (buf0) and 1 (buf1): G0, G1 ----
    #pragma unroll
    for (int c = 0; c < 2; ++c) {
        #pragma unroll
        for (int t = 0; t < 8; ++t)       // A rows: prow + 16t
            cp_async16(dA0 + c * CHUNK + t * 2048,
                       sA0 + c * 64 + (size_t)t * 16 * 512);
        #pragma unroll
        for (int t = 0; t < 8; ++t)       // B rows: prow + 16t
            cp_async16(dB0 + c * CHUNK + t * 2048,
                       sB0 + c * 64 + (size_t)t * 16 * 512);
        CP_COMMIT();
    }

    // ---- load C tile (plain LDG, overlaps cp.async): Cs[i_local][j_local][z] ----
    {
        const float* Cg = y_pred + 1536 + 2ull * 512 * 4096;
        const int i0 = ntile * 16, j0 = mtile * 16;
        float* Cs = (float*)(dyn + OFF_C);
        #pragma unroll
        for (int u = 0; u < 4; ++u) {
            int idx = tid + u * 128;          // 512 float4
            int ii = idx >> 5, rem = idx & 31;
            int jj = rem >> 1, half = rem & 1;
            float4 d = *(const float4*)(Cg + (((size_t)(i0 + ii) * 512 + (j0 + jj)) * 8 + half * 4));
            *(float4*)(Cs + ((ii * 16 + jj) * 8 + half * 4)) = d;
        }
    }

    // ---- lane-fixed fragment geometry (warp tile 64x64) ----
    // Algebraic swizzle hoist: for x = row*128 + c (c < 128),
    //   SWZ128(x) = row*128 + (c ^ ((row&7)<<4)),
    // and row&7 == rowin for ALL fragment rows (offsets are multiples of 8).
    const int sub = lid >> 3, rowin = lid & 7;
    const int a_row = wm * 64 + (sub & 1) * 8 + rowin;   // + mf*16, mf<4
    const int b_row = wn * 64 + (sub & 1) * 8 + rowin;   // + nb*8,  nb<8
    const int ksub  = (sub >> 1) * 8;                    // + ks*16
    const uint32_t xm = (uint32_t)(rowin << 4);
    uint32_t csw[4];
    #pragma unroll
    for (int ks = 0; ks < 4; ++ks)
        csw[ks] = ((uint32_t)((ks * 16 + ksub) * 2)) ^ xm;
    const uint32_t aoff0 = (uint32_t)(a_row * 128);
    const uint32_t boff0 = (uint32_t)(b_row * 128);

    uint32_t acc[4][8][2];                   // fp16x2 accumulators (64 regs)
    #pragma unroll
    for (int mf = 0; mf < 4; ++mf)
        #pragma unroll
        for (int nf = 0; nf < 8; ++nf) { acc[mf][nf][0] = 0u; acc[mf][nf][1] = 0u; }

    // ---- K loop: 8 chunks of 64, 2-buffer ping-pong.
    //      Pending {Gc, G(c+1)} -> WAIT(1) retires Gc (WAIT(0) at c=7).
    //      Second barrier retires buf reads before the c+2 prefetch overwrites.
    #pragma unroll 1
    for (int c = 0; c < 8; ++c) {
        if (c < 7) { CP_WAIT(1); } else { CP_WAIT(0); }
        __syncthreads();

        const int b = c & 1;
        const uint32_t abuf = dbase + b * CHUNK + aoff0;
        const uint32_t bbuf = dbase + OFF_B0 + b * CHUNK + boff0;

        #pragma unroll
        for (int ks = 0; ks < 4; ++ks) {
            const uint32_t cs = csw[ks];
            uint32_t afr[4][4];
            #pragma unroll
            for (int mf = 0; mf < 4; ++mf)
                ldmatrix_x4(abuf + (uint32_t)(mf * 2048) + cs,
                            afr[mf][0], afr[mf][1], afr[mf][2], afr[mf][3]);
            uint32_t b0[8], b1[8];
            #pragma unroll
            for (int nb = 0; nb < 8; nb += 2) {
                uint32_t r0, r1, r2, r3;
                ldmatrix_x4(bbuf + (uint32_t)(nb * 1024) + cs, r0, r1, r2, r3);
                b0[nb] = r0; b0[nb + 1] = r1; b1[nb] = r2; b1[nb + 1] = r3;
            }
            #pragma unroll
            for (int mf = 0; mf < 4; ++mf)
                #pragma unroll
                for (int nf = 0; nf < 8; ++nf)
                    mma16816_f16(acc[mf][nf], afr[mf], b0[nf], b1[nf]);
        }
        __syncthreads();                     // buf reads retired

        if (c < 6) {                         // prefetch chunk c+2 into buf b
            const int kb = (c + 2) * 64;
            #pragma unroll
            for (int t = 0; t < 8; ++t)
                cp_async16(dA0 + b * CHUNK + t * 2048,
                           sA0 + kb + (size_t)t * 16 * 512);
            #pragma unroll
            for (int t = 0; t < 8; ++t)
                cp_async16(dB0 + b * CHUNK + t * 2048,
                           sB0 + kb + (size_t)t * 16 * 512);
            CP_COMMIT();
        }
    }

    // ---- s_probs lives in dynamic smem, aliased over the (dead) A/B buffers ----
    float* sp = (float*)dyn;                 // 512 floats at offset 0
    #pragma unroll
    for (int q = 0; q < 4; ++q) sp[tid + q * 128] = 0.0f;
    __syncthreads();

    // ---- fused epilogue: probs[x,y,z] += D * C ----
    // x = lid>>2; y-pair cc; j_local = wm*8+mf*2+rp; i_local = wn*8+nf
    {
        const float* Cs = (const float*)(dyn + OFF_C);
        float partial[2][8];
        #pragma unroll
        for (int cc = 0; cc < 2; ++cc)
            #pragma unroll
            for (int z = 0; z < 8; ++z) partial[cc][z] = 0.0f;

        #pragma unroll
        for (int mf = 0; mf < 4; ++mf)
            #pragma unroll
            for (int rp = 0; rp < 2; ++rp) {
                const int j = wm * 8 + mf * 2 + rp;
                #pragma unroll
                for (int nf = 0; nf < 8; ++nf) {
                    const int i = wn * 8 + nf;
                    const float* cp = Cs + ((i * 16 + j) * 8);
                    float4 cA = *(const float4*)cp;
                    float4 cB = *(const float4*)(cp + 4);
                    const __half2 h = *(const __half2*)&acc[mf][nf][rp];
                    const float vlo = __low2float(h);    // col cc=0
                    const float vhi = __high2float(h);   // col cc=1
                    partial[0][0] = fmaf(vlo, cA.x, partial[0][0]);
                    partial[0][1] = fmaf(vlo, cA.y, partial[0][1]);
                    partial[0][2] = fmaf(vlo, cA.z, partial[0][2]);
                    partial[0][3] = fmaf(vlo, cA.w, partial[0][3]);
                    partial[0][4] = fmaf(vlo, cB.x, partial[0][4]);
                    partial[0][5] = fmaf(vlo, cB.y, partial[0][5]);
                    partial[0][6] = fmaf(vlo, cB.z, partial[0][6]);
                    partial[0][7] = fmaf(vlo, cB.w, partial[0][7]);
                    partial[1][0] = fmaf(vhi, cA.x, partial[1][0]);
                    partial[1][1] = fmaf(vhi, cA.y, partial[1][1]);
                    partial[1][2] = fmaf(vhi, cA.z, partial[1][2]);
                    partial[1][3] = fmaf(vhi, cA.w, partial[1][3]);
                    partial[1][4] = fmaf(vhi, cB.x, partial[1][4]);
                    partial[1][5] = fmaf(vhi, cB.y, partial[1][5]);
                    partial[1][6] = fmaf(vhi, cB.z, partial[1][6]);
                    partial[1][7] = fmaf(vhi, cB.w, partial[1][7]);
                }
            }

        const int x = lid >> 2;
        const int ybase = 2 * (lid & 3);
        #pragma unroll
        for (int cc = 0; cc < 2; ++cc)
            #pragma unroll
            for (int z = 0; z < 8; ++z)
                atomicAdd(&sp[x * 64 + (ybase + cc) * 8 + z], partial[cc][z]);
    }
    __syncthreads();

    #pragma unroll
    for (int q = 0; q < 4; ++q)
        atomicAdd(&g_probs[tid + q * 128], sp[tid + q * 128]);

    // ---- last-block fused finalize: KL divergence + emit (d, probs) ----
    __threadfence();
    if (tid == 0) s_last = atomicAdd(&g_ctr, 1u);
    __syncthreads();
    if (s_last == (unsigned)(gridDim.x - 1)) {
        __threadfence();
        float p[4], term = 0.0f;
        #pragma unroll
        for (int q = 0; q < 4; ++q) {
            p[q] = g_probs[tid + q * 128];
            const float pc = fminf(fmaxf(p[q], 1e-10f), 1.0f);
            const float yt = y_true[tid + q * 128];
            term += yt * (logf(yt + 1e-10f) - logf(pc));
        }

        #pragma unroll
        for (int o = 16; o; o >>= 1) term += __shfl_xor_sync(0xFFFFFFFFu, term, o);
        if (lid == 0) red[wid] = term;
        __syncthreads();

        float d = 0.0f;
        if (tid < 4) {
            float v = red[tid];
            v += __shfl_xor_sync(0xFu, v, 2);
            v += __shfl_xor_sync(0xFu, v, 1);
            d = v;
        }

        if (out_size >= 513) {
            if (tid == 0) out[0] = d;
            #pragma unroll
            for (int q = 0; q < 4; ++q) out[1 + tid + q * 128] = p[q];
        } else if (out_size == 512) {
            #pragma unroll
            for (int q = 0; q < 4; ++q) out[tid + q * 128] = p[q];
        } else if (out_size >= 1) {
            if (tid == 0) out[0] = d;
        }
    }
}

// ============================================================================
extern "C" void kernel_launch(void* const* d_in, const int* in_sizes, int n_in,
                              void* d_out, int out_size) {
    const float* y_pred = (const float*)d_in[0];
    const float* y_true = (const float*)d_in[1];
    float* out = (float*)d_out;

    cudaFuncSetAttribute(gemm_kernel,
                         cudaFuncAttributeMaxDynamicSharedMemorySize, GEMM_SMEM);

    conv_kernel<<<1024, 256>>>(y_pred);
    gemm_kernel<<<1024, 128, GEMM_SMEM>>>(y_pred, y_true, out, out_size);
}